// round 5
// baseline (speedup 1.0000x reference)
#include <cuda_runtime.h>
#include <cstdint>

#define Bb 32
#define Qn 300
#define Mn 50
#define NCLS 92
#define BQ (Bb*Qn)      // 9600
#define BM (Bb*Mn)      // 1600
#define RPB 8
#define NCOSTBLK (BQ/RPB)   // 1200
#define PITCH 301
#define DSMEM 73728

// fallback scratch if out buffer holds only C
__device__ float g_idx_scratch[2*BM];

// ---------------------------------------------------------------------------
// Fused kernel: blocks [0,32) run per-batch Hungarian (with locally-computed
// diagonal cost tile), blocks [32, 1232) compute the full cross cost matrix.
// ---------------------------------------------------------------------------
__global__ void __launch_bounds__(256) fused_kernel(
    const float*  __restrict__ logits,
    const float4* __restrict__ pboxes,
    const int*    __restrict__ tlab,
    const float4* __restrict__ tboxes,
    float* __restrict__ Cout,
    float* __restrict__ outPred,
    float* __restrict__ outGt)
{
  extern __shared__ char smem[];
  int tid  = threadIdx.x;
  int lane = tid & 31;
  int warp = tid >> 5;

  if (blockIdx.x >= Bb) {
    // ================= cost role: 8 pred rows x 1600 target cols =========
    float4* s_txy   = (float4*)smem;                 // [1600] xyxy
    float*  s_ta    = (float*)(smem + 25600);        // [1600]
    int*    s_tl    = (int*)(smem + 32000);          // [1600]
    float*  s_prows = (float*)(smem + 38400);        // [8][92]
    int rowbase = (blockIdx.x - Bb) * RPB;

    for (int c = tid; c < BM; c += 256) {
      float4 tb = tboxes[c];
      float x1 = tb.x - 0.5f*tb.z, y1 = tb.y - 0.5f*tb.w;
      float x2 = tb.x + 0.5f*tb.z, y2 = tb.y + 0.5f*tb.w;
      s_txy[c] = make_float4(x1, y1, x2, y2);
      s_ta[c]  = (x2 - x1) * (y2 - y1);
      s_tl[c]  = tlab[c];
    }
    // fused softmax: warp w -> row rowbase+w
    {
      const float* xr = logits + (size_t)(rowbase + warp) * NCLS;
      float x0 = xr[lane];
      float x1 = xr[lane + 32];
      float x2 = (lane < NCLS - 64) ? xr[lane + 64] : -1e30f;
      float mx = fmaxf(x0, fmaxf(x1, x2));
      #pragma unroll
      for (int o = 16; o > 0; o >>= 1) mx = fmaxf(mx, __shfl_xor_sync(~0u, mx, o));
      float e0 = __expf(x0 - mx);
      float e1 = __expf(x1 - mx);
      float e2 = (lane < NCLS - 64) ? __expf(x2 - mx) : 0.f;
      float s = e0 + e1 + e2;
      #pragma unroll
      for (int o = 16; o > 0; o >>= 1) s += __shfl_xor_sync(~0u, s, o);
      float inv = __fdividef(1.f, s);
      float* pr = s_prows + warp * NCLS;
      pr[lane]      = e0 * inv;
      pr[lane + 32] = e1 * inv;
      if (lane < NCLS - 64) pr[lane + 64] = e2 * inv;
    }
    __syncthreads();

    for (int rr = 0; rr < RPB; rr++) {
      int row = rowbase + rr;
      float4 pbv = pboxes[row];
      float px1 = pbv.x - 0.5f*pbv.z, py1 = pbv.y - 0.5f*pbv.w;
      float px2 = pbv.x + 0.5f*pbv.z, py2 = pbv.y + 0.5f*pbv.w;
      float pa  = (px2 - px1) * (py2 - py1);
      const float* prow = s_prows + rr * NCLS;
      float* Crow = Cout + (size_t)row * BM;
      for (int c = tid; c < BM; c += 256) {
        float4 tb = tboxes[c];       // L1-resident
        float cb = fabsf(pbv.x - tb.x) + fabsf(pbv.y - tb.y)
                 + fabsf(pbv.z - tb.z) + fabsf(pbv.w - tb.w);
        float4 t = s_txy[c];
        float iw = fmaxf(fminf(px2, t.z) - fmaxf(px1, t.x), 0.f);
        float ih = fmaxf(fminf(py2, t.w) - fmaxf(py1, t.y), 0.f);
        float inter = iw * ih;
        float uni = pa + s_ta[c] - inter;
        float ew = fmaxf(fmaxf(px2, t.z) - fminf(px1, t.x), 0.f);
        float eh = fmaxf(fmaxf(py2, t.w) - fminf(py1, t.y), 0.f);
        float ae = ew * eh;
        float giou = __fdividef(inter, uni) - __fdividef(ae - uni, ae);
        float cc = -prow[s_tl[c]];
        Crow[c] = fmaf(5.f, cb, cc) - 2.f * giou;
      }
    }
    return;
  }

  // ================= Hungarian role: one block per batch ==================
  int b = blockIdx.x;
  float*  cost_s = (float*)smem;                    // [50][301]
  float4* s_pxy  = (float4*)(smem + 60208);         // [300] pred xyxy
  float4* s_txy  = (float4*)(smem + 65008);         // [50]  tgt xyxy
  float*  s_pa   = (float*)(smem + 65808);          // [300]
  float*  s_ta   = (float*)(smem + 67008);          // [50]
  float2* s_stat = (float2*)(smem + 67208);         // [300] (mx, inv)
  float*  u_s    = (float*)(smem + 69608);          // [51]
  int*    p_s    = (int*)(smem + 69812);            // [301]
  int*    way_s  = (int*)(smem + 71016);            // [300]
  int*    q_s    = (int*)(smem + 72216);            // [50]
  int*    s_tl   = (int*)(smem + 72416);            // [50]
  float4* s_tb   = (float4*)(smem + 72624);         // [50] raw cxcywh

  if (tid < Mn) {
    float4 tb = tboxes[b*Mn + tid];
    s_tb[tid] = tb;
    float x1 = tb.x - 0.5f*tb.z, y1 = tb.y - 0.5f*tb.w;
    float x2 = tb.x + 0.5f*tb.z, y2 = tb.y + 0.5f*tb.w;
    s_txy[tid] = make_float4(x1, y1, x2, y2);
    s_ta[tid]  = (x2 - x1) * (y2 - y1);
    s_tl[tid]  = tlab[b*Mn + tid];
  }
  for (int q = tid; q < Qn; q += 256) {
    float4 pb = pboxes[b*Qn + q];
    float x1 = pb.x - 0.5f*pb.z, y1 = pb.y - 0.5f*pb.w;
    float x2 = pb.x + 0.5f*pb.z, y2 = pb.y + 0.5f*pb.w;
    s_pxy[q] = make_float4(x1, y1, x2, y2);
    s_pa[q]  = (x2 - x1) * (y2 - y1);
  }
  if (tid <= Mn) u_s[tid] = 0.f;
  for (int j = tid; j <= Qn; j += 256) p_s[j] = -1;
  // softmax stats (mx, 1/sum) per query row, warp per row
  for (int q = warp; q < Qn; q += 8) {
    const float* xr = logits + (size_t)(b*Qn + q) * NCLS;
    float x0 = xr[lane];
    float x1 = xr[lane + 32];
    float x2 = (lane < NCLS - 64) ? xr[lane + 64] : -1e30f;
    float mx = fmaxf(x0, fmaxf(x1, x2));
    #pragma unroll
    for (int o = 16; o > 0; o >>= 1) mx = fmaxf(mx, __shfl_xor_sync(~0u, mx, o));
    float e0 = __expf(x0 - mx);
    float e1 = __expf(x1 - mx);
    float e2 = (lane < NCLS - 64) ? __expf(x2 - mx) : 0.f;
    float s = e0 + e1 + e2;
    #pragma unroll
    for (int o = 16; o > 0; o >>= 1) s += __shfl_xor_sync(~0u, s, o);
    if (lane == 0) s_stat[q] = make_float2(mx, __fdividef(1.f, s));
  }
  __syncthreads();

  // fill local diagonal cost tile cost_s[t][q]
  for (int idx = tid; idx < Mn * Qn; idx += 256) {
    int q = idx / Mn, t = idx - q * Mn;
    float2 st = s_stat[q];
    float lg = logits[(size_t)(b*Qn + q) * NCLS + s_tl[t]];
    float cc = -__expf(lg - st.x) * st.y;
    float4 pb = pboxes[b*Qn + q];
    float4 tb = s_tb[t];
    float cb = fabsf(pb.x - tb.x) + fabsf(pb.y - tb.y)
             + fabsf(pb.z - tb.z) + fabsf(pb.w - tb.w);
    float4 p = s_pxy[q];
    float4 tx = s_txy[t];
    float iw = fmaxf(fminf(p.z, tx.z) - fmaxf(p.x, tx.x), 0.f);
    float ih = fmaxf(fminf(p.w, tx.w) - fmaxf(p.y, tx.y), 0.f);
    float inter = iw * ih;
    float uni = s_pa[q] + s_ta[t] - inter;
    float ew = fmaxf(fmaxf(p.z, tx.z) - fminf(p.x, tx.x), 0.f);
    float eh = fmaxf(fmaxf(p.w, tx.w) - fminf(p.y, tx.y), 0.f);
    float ae = ew * eh;
    float giou = __fdividef(inter, uni) - __fdividef(ae - uni, ae);
    cost_s[t * PITCH + q] = fmaf(5.f, cb, cc) - 2.f * giou;
  }
  __syncthreads();
  if (warp != 0) return;

  // ---- single-warp JV solver: lane owns columns lane+32k, k<10 ----------
  float minv[10], vcol[10];
  #pragma unroll
  for (int k = 0; k < 10; k++) vcol[k] = 0.f;

  for (int i = 0; i < Mn; i++) {
    unsigned usedmask = 0;
    #pragma unroll
    for (int k = 0; k < 10; k++) minv[k] = 1e30f;
    if (lane == 0) p_s[Qn] = i;
    __syncwarp();
    int j0 = Qn;
    while (true) {
      if (j0 < Qn && lane == (j0 & 31)) usedmask |= 1u << (j0 >> 5);
      int i0 = p_s[j0];
      float ui0 = u_s[i0];
      const float* crow = cost_s + i0 * PITCH;
      float bestv = 1e30f;
      unsigned bestc = 0xffffffffu;
      #pragma unroll
      for (int k = 0; k < 10; k++) {
        int col = lane + 32 * k;
        if (col < Qn && !((usedmask >> k) & 1)) {
          float cur = crow[col] - ui0 - vcol[k];
          if (cur < minv[k]) { minv[k] = cur; way_s[col] = j0; }
          if (minv[k] < bestv) { bestv = minv[k]; bestc = (unsigned)col; }
        }
      }
      unsigned fb = __float_as_uint(bestv);
      fb = (fb & 0x80000000u) ? ~fb : (fb | 0x80000000u);
      unsigned gmin = __reduce_min_sync(0xffffffffu, fb);
      unsigned csel = (fb == gmin) ? bestc : 0xffffffffu;
      int j1 = (int)__reduce_min_sync(0xffffffffu, csel);
      unsigned gd = (gmin & 0x80000000u) ? (gmin & 0x7fffffffu) : ~gmin;
      float delta = __uint_as_float(gd);
      #pragma unroll
      for (int k = 0; k < 10; k++) {
        int col = lane + 32 * k;
        if (col < Qn) {
          if ((usedmask >> k) & 1) {
            vcol[k] -= delta;
            u_s[p_s[col]] += delta;   // distinct rows per used column
          } else {
            minv[k] -= delta;
          }
        }
      }
      if (lane == 0) u_s[i] += delta;  // virtual column m (p[m] = i)
      __syncwarp();
      j0 = j1;
      if (p_s[j0] == -1) break;
    }
    if (lane == 0) {     // augment along 'way' chain
      int j = j0;
      while (j != Qn) { int jn = way_s[j]; p_s[j] = p_s[jn]; j = jn; }
    }
    __syncwarp();
  }

  // col_of_row + rank-sort (50 distinct ints), warp 0 only
  for (int j = lane; j < Qn; j += 32) {
    int r = p_s[j];
    if (r >= 0) q_s[r] = j;
  }
  __syncwarp();
  for (int t = lane; t < Mn; t += 32) {
    int myq = q_s[t];
    int rank = 0;
    #pragma unroll 1
    for (int t2 = 0; t2 < Mn; t2++) rank += (q_s[t2] < myq) ? 1 : 0;
    outPred[b * Mn + rank] = (float)myq;
    outGt[b * Mn + rank]   = (float)t;
  }
}

// ---------------------------------------------------------------------------
extern "C" void kernel_launch(void* const* d_in, const int* in_sizes, int n_in,
                              void* d_out, int out_size) {
  const float*  logits = (const float*)d_in[0];
  const float4* pboxes = (const float4*)d_in[1];
  const int*    tlab   = (const int*)d_in[2];
  const float4* tboxes = (const float4*)d_in[3];
  float* out = (float*)d_out;

  float *outPred, *outGt, *Cbase;
  if (out_size >= 2 * BM + BQ * BM) {
    outPred = out;
    outGt   = out + BM;
    Cbase   = out + 2 * BM;
  } else {
    void* sp = nullptr;
    cudaGetSymbolAddress(&sp, g_idx_scratch);
    outPred = (float*)sp;
    outGt   = outPred + BM;
    Cbase   = out;
  }

  cudaFuncSetAttribute(fused_kernel,
                       cudaFuncAttributeMaxDynamicSharedMemorySize, DSMEM);
  fused_kernel<<<Bb + NCOSTBLK, 256, DSMEM>>>(logits, pboxes, tlab, tboxes,
                                              Cbase, outPred, outGt);
}